// round 11
// baseline (speedup 1.0000x reference)
#include <cuda_runtime.h>
#include <math.h>

#define BATCH 8
#define DET   512
#define NANG  180
#define PADW  768
#define POFF  128
#define NROWS (BATCH * NANG)

__device__ float g_filt2[1024];
// Lerp lines per padded cell d: (A, B), value(yc) = A + B*yc, yc = yi - 256.
// A = v0 - (d - 384)*B   (384 = POFF + 256)
__device__ float2 g_lines[NROWS * PADW];

__global__ void init_g_kernel() {
    int k = blockIdx.x * blockDim.x + threadIdx.x;
    if (k >= 1024) return;
    int m = k - 512; if (m < 0) m = -m;
    float v = 0.0f;
    if (m == 0) v = 0.5f;
    else if (m & 1) {
        double pm = 3.141592653589793 * (double)m;
        v = (float)(-2.0 / (pm * pm));
    }
    g_filt2[k] = v;
}

// Zero only the pad regions of g_lines: cells [0,128) and [640,768) per row.
__global__ void zero_pads_kernel() {
    int idx = blockIdx.x * blockDim.x + threadIdx.x;
    if (idx >= NROWS * 256) return;
    int row = idx >> 8;
    int c   = idx & 255;
    int d   = (c < 128) ? c : (640 + (c - 128));
    g_lines[row * PADW + d] = make_float2(0.0f, 0.0f);
}

// Ramp filter (symmetric Toeplitz matvec, parity split) fused with line build.
// Computes 9 accumulators (d..d+8) so B = y[d+1]-y[d] is local.
__global__ void __launch_bounds__(192) filt_kernel(const float* __restrict__ x) {
    __shared__ float gs[1024];
    for (int i = threadIdx.x; i < 1024; i += 192) gs[i] = g_filt2[i];
    __syncthreads();

    int b = blockIdx.y;
    int dbase = blockIdx.x * 8;        // always even
    int a = threadIdx.x;
    if (a >= NANG) return;

    const float* xb = x + (size_t)b * DET * NANG + a;
    bool has8 = (dbase < DET - 8);

    float acc0 = 0.5f * xb[(dbase + 0) * NANG];
    float acc1 = 0.5f * xb[(dbase + 1) * NANG];
    float acc2 = 0.5f * xb[(dbase + 2) * NANG];
    float acc3 = 0.5f * xb[(dbase + 3) * NANG];
    float acc4 = 0.5f * xb[(dbase + 4) * NANG];
    float acc5 = 0.5f * xb[(dbase + 5) * NANG];
    float acc6 = 0.5f * xb[(dbase + 6) * NANG];
    float acc7 = 0.5f * xb[(dbase + 7) * NANG];
    float acc8 = has8 ? 0.5f * xb[(dbase + 8) * NANG] : 0.0f;

    const float* gp = gs + 512 + dbase;
    const float* xr = xb;

    #pragma unroll 4
    for (int j = 0; j < DET; j += 2) {
        float xe = xr[0];
        float xo = xr[NANG];
        xr += 2 * NANG;
        const float* g0 = gp - j;
        float gm1 = g0[-1], g1 = g0[1], g3 = g0[3], g5 = g0[5], g7 = g0[7];
        acc1 = fmaf(g1, xe, acc1);
        acc3 = fmaf(g3, xe, acc3);
        acc5 = fmaf(g5, xe, acc5);
        acc7 = fmaf(g7, xe, acc7);
        acc0 = fmaf(gm1, xo, acc0);
        acc2 = fmaf(g1,  xo, acc2);
        acc4 = fmaf(g3,  xo, acc4);
        acc6 = fmaf(g5,  xo, acc6);
        acc8 = fmaf(g7,  xo, acc8);
    }
    if (!has8) acc8 = 0.0f;    // d+8 = 512 is the zero pad

    float2* out = g_lines + ((size_t)b * NANG + a) * PADW + POFF + dbase;
    float fb = (float)(dbase - 256);
    float B0 = acc1 - acc0;  out[0] = make_float2(fmaf(-(fb + 0.f), B0, acc0), B0);
    float B1 = acc2 - acc1;  out[1] = make_float2(fmaf(-(fb + 1.f), B1, acc1), B1);
    float B2 = acc3 - acc2;  out[2] = make_float2(fmaf(-(fb + 2.f), B2, acc2), B2);
    float B3 = acc4 - acc3;  out[3] = make_float2(fmaf(-(fb + 3.f), B3, acc3), B3);
    float B4 = acc5 - acc4;  out[4] = make_float2(fmaf(-(fb + 4.f), B4, acc4), B4);
    float B5 = acc6 - acc5;  out[5] = make_float2(fmaf(-(fb + 5.f), B5, acc5), B5);
    float B6 = acc7 - acc6;  out[6] = make_float2(fmaf(-(fb + 6.f), B6, acc6), B6);
    float B7 = acc8 - acc7;  out[7] = make_float2(fmaf(-(fb + 7.f), B7, acc7), B7);
    if (dbase == 0) {
        // left boundary cell d=127: v0 = 0, v1 = y[0]  ->  B = acc0, A = 257*B
        out[-1] = make_float2(257.0f * acc0, acc0);
    }
}

// Backprojection: 8 pixels/thread (iy0 + 8k), 6-instr taps, 8 loads in flight.
__global__ void __launch_bounds__(256) bp_kernel(float* __restrict__ out) {
    __shared__ float2 cs[NANG];
    int tid = threadIdx.y * 32 + threadIdx.x;
    if (tid < NANG) {
        float th = (float)tid * 0.017453292519943295f;
        float s, c;
        sincosf(th, &s, &c);
        cs[tid] = make_float2(c * 255.5f, s * 255.5f);
    }
    __syncthreads();

    int b   = blockIdx.z;
    int ix  = blockIdx.x * 32 + threadIdx.x;
    int iy0 = blockIdx.y * 64 + threadIdx.y;   // pixels iy0 + {0,8,...,56}

    const float step = 2.0f / 511.0f;
    // no-FMA grid coords to track jnp.linspace rounding (mask sensitivity)
    float ux = __fadd_rn(__fmul_rn((float)ix, step), -1.0f);
    float uy[8], nuy[8];
    #pragma unroll
    for (int k = 0; k < 8; k++) {
        uy[k]  = __fadd_rn(__fmul_rn((float)(iy0 + 8 * k), step), -1.0f);
        nuy[k] = -uy[k];
    }

    // +384 (POFF + 256) folded into the row pointer; j is signed.
    const float2* p = g_lines + (size_t)b * NANG * PADW + 384;

    float acc[8];
    #pragma unroll
    for (int k = 0; k < 8; k++) acc[k] = 0.0f;

    #pragma unroll 2
    for (int a = 0; a < NANG; a++, p += PADW) {
        float2 t = cs[a];
        // yc = ux*t.x - uy*t.y - 0.5   (= yi - 256)
        float xb = fmaf(ux, t.x, -0.5f);

        float yc[8];
        int   j[8];
        #pragma unroll
        for (int k = 0; k < 8; k++) yc[k] = fmaf(nuy[k], t.y, xb);
        #pragma unroll
        for (int k = 0; k < 8; k++) j[k] = __float2int_rd(yc[k]);

        float2 q[8];
        #pragma unroll
        for (int k = 0; k < 8; k++) q[k] = p[j[k]];
        #pragma unroll
        for (int k = 0; k < 8; k++) acc[k] += fmaf(q[k].y, yc[k], q[k].x);
    }

    const float scale = 0.008726646259971648f;  // pi/360
    float uxx = __fmul_rn(ux, ux);
    float* o = out + ((size_t)b * 512 + iy0) * 512 + ix;
    #pragma unroll
    for (int k = 0; k < 8; k++) {
        float r2 = __fadd_rn(uxx, __fmul_rn(uy[k], uy[k]));
        o[k * 8 * 512] = (r2 <= 1.0f) ? acc[k] * scale : 0.0f;
    }
}

extern "C" void kernel_launch(void* const* d_in, const int* in_sizes, int n_in,
                              void* d_out, int out_size) {
    const float* x = (const float*)d_in[0];
    float* out = (float*)d_out;

    init_g_kernel<<<2, 512>>>();
    zero_pads_kernel<<<(NROWS * 256 + 255) / 256, 256>>>();
    filt_kernel<<<dim3(DET / 8, BATCH), 192>>>(x);
    bp_kernel<<<dim3(512 / 32, 512 / 64, BATCH), dim3(32, 8)>>>(out);
}

// round 12
// speedup vs baseline: 1.3191x; 1.3191x over previous
#include <cuda_runtime.h>
#include <math.h>

#define BATCH 8
#define DET   512
#define NANG  180
#define PADW  768
#define POFF  128
#define NROWS (BATCH * NANG)

__device__ float g_filt2[1024];
// Lerp lines per padded cell d: (A, B), value(yc) = A + B*yc, yc = yi - 256.
// A = v0 - (d - 384)*B   (384 = POFF + 256)
__device__ float2 g_lines[NROWS * PADW];

__global__ void init_g_kernel() {
    int k = blockIdx.x * blockDim.x + threadIdx.x;
    if (k >= 1024) return;
    int m = k - 512; if (m < 0) m = -m;
    float v = 0.0f;
    if (m == 0) v = 0.5f;
    else if (m & 1) {
        double pm = 3.141592653589793 * (double)m;
        v = (float)(-2.0 / (pm * pm));
    }
    g_filt2[k] = v;
}

// Zero only the pad regions of g_lines: cells [0,128) and [640,768) per row.
__global__ void zero_pads_kernel() {
    int idx = blockIdx.x * blockDim.x + threadIdx.x;
    if (idx >= NROWS * 256) return;
    int row = idx >> 8;
    int c   = idx & 255;
    int d   = (c < 128) ? c : (640 + (c - 128));
    g_lines[row * PADW + d] = make_float2(0.0f, 0.0f);
}

// Ramp filter (symmetric Toeplitz matvec, parity split) fused with line build.
// Computes 9 accumulators (d..d+8) so B = y[d+1]-y[d] is local.
__global__ void __launch_bounds__(192) filt_kernel(const float* __restrict__ x) {
    __shared__ float gs[1024];
    for (int i = threadIdx.x; i < 1024; i += 192) gs[i] = g_filt2[i];
    __syncthreads();

    int b = blockIdx.y;
    int dbase = blockIdx.x * 8;        // always even
    int a = threadIdx.x;
    if (a >= NANG) return;

    const float* xb = x + (size_t)b * DET * NANG + a;
    bool has8 = (dbase < DET - 8);

    float acc0 = 0.5f * xb[(dbase + 0) * NANG];
    float acc1 = 0.5f * xb[(dbase + 1) * NANG];
    float acc2 = 0.5f * xb[(dbase + 2) * NANG];
    float acc3 = 0.5f * xb[(dbase + 3) * NANG];
    float acc4 = 0.5f * xb[(dbase + 4) * NANG];
    float acc5 = 0.5f * xb[(dbase + 5) * NANG];
    float acc6 = 0.5f * xb[(dbase + 6) * NANG];
    float acc7 = 0.5f * xb[(dbase + 7) * NANG];
    float acc8 = has8 ? 0.5f * xb[(dbase + 8) * NANG] : 0.0f;

    const float* gp = gs + 512 + dbase;
    const float* xr = xb;

    #pragma unroll 4
    for (int j = 0; j < DET; j += 2) {
        float xe = xr[0];
        float xo = xr[NANG];
        xr += 2 * NANG;
        const float* g0 = gp - j;
        float gm1 = g0[-1], g1 = g0[1], g3 = g0[3], g5 = g0[5], g7 = g0[7];
        acc1 = fmaf(g1, xe, acc1);
        acc3 = fmaf(g3, xe, acc3);
        acc5 = fmaf(g5, xe, acc5);
        acc7 = fmaf(g7, xe, acc7);
        acc0 = fmaf(gm1, xo, acc0);
        acc2 = fmaf(g1,  xo, acc2);
        acc4 = fmaf(g3,  xo, acc4);
        acc6 = fmaf(g5,  xo, acc6);
        acc8 = fmaf(g7,  xo, acc8);
    }
    if (!has8) acc8 = 0.0f;    // d+8 = 512 is the zero pad

    float2* out = g_lines + ((size_t)b * NANG + a) * PADW + POFF + dbase;
    float fb = (float)(dbase - 256);
    float B0 = acc1 - acc0;  out[0] = make_float2(fmaf(-(fb + 0.f), B0, acc0), B0);
    float B1 = acc2 - acc1;  out[1] = make_float2(fmaf(-(fb + 1.f), B1, acc1), B1);
    float B2 = acc3 - acc2;  out[2] = make_float2(fmaf(-(fb + 2.f), B2, acc2), B2);
    float B3 = acc4 - acc3;  out[3] = make_float2(fmaf(-(fb + 3.f), B3, acc3), B3);
    float B4 = acc5 - acc4;  out[4] = make_float2(fmaf(-(fb + 4.f), B4, acc4), B4);
    float B5 = acc6 - acc5;  out[5] = make_float2(fmaf(-(fb + 5.f), B5, acc5), B5);
    float B6 = acc7 - acc6;  out[6] = make_float2(fmaf(-(fb + 6.f), B6, acc6), B6);
    float B7 = acc8 - acc7;  out[7] = make_float2(fmaf(-(fb + 7.f), B7, acc7), B7);
    if (dbase == 0) {
        // left boundary cell d=127: v0 = 0, v1 = y[0]  ->  B = acc0, A = 257*B
        out[-1] = make_float2(257.0f * acc0, acc0);
    }
}

// Backprojection: 4 pixels/thread (iy0 + {0,8,16,24}), 6-instr taps.
__global__ void __launch_bounds__(256) bp_kernel(float* __restrict__ out) {
    __shared__ float2 cs[NANG];
    int tid = threadIdx.y * 32 + threadIdx.x;
    if (tid < NANG) {
        float th = (float)tid * 0.017453292519943295f;
        float s, c;
        sincosf(th, &s, &c);
        cs[tid] = make_float2(c * 255.5f, s * 255.5f);
    }
    __syncthreads();

    int b   = blockIdx.z;
    int ix  = blockIdx.x * 32 + threadIdx.x;
    int iy0 = blockIdx.y * 32 + threadIdx.y;   // pixels iy0, +8, +16, +24

    const float step = 2.0f / 511.0f;
    // no-FMA grid coords to track jnp.linspace rounding (mask sensitivity)
    float ux  = __fadd_rn(__fmul_rn((float)ix,        step), -1.0f);
    float uy0 = __fadd_rn(__fmul_rn((float)(iy0),      step), -1.0f);
    float uy1 = __fadd_rn(__fmul_rn((float)(iy0 + 8),  step), -1.0f);
    float uy2 = __fadd_rn(__fmul_rn((float)(iy0 + 16), step), -1.0f);
    float uy3 = __fadd_rn(__fmul_rn((float)(iy0 + 24), step), -1.0f);
    float nuy0 = -uy0, nuy1 = -uy1, nuy2 = -uy2, nuy3 = -uy3;

    // +384 (POFF + 256) folded into the row pointer; j is signed.
    const float2* p = g_lines + (size_t)b * NANG * PADW + 384;

    float acc0 = 0.0f, acc1 = 0.0f, acc2 = 0.0f, acc3 = 0.0f;
    #pragma unroll 4
    for (int a = 0; a < NANG; a++, p += PADW) {
        float2 t = cs[a];
        // yc = ux*t.x - uy*t.y - 0.5   (= yi - 256)
        float xb = fmaf(ux, t.x, -0.5f);

        float yc0 = fmaf(nuy0, t.y, xb);
        float yc1 = fmaf(nuy1, t.y, xb);
        float yc2 = fmaf(nuy2, t.y, xb);
        float yc3 = fmaf(nuy3, t.y, xb);

        int j0 = __float2int_rd(yc0);
        int j1 = __float2int_rd(yc1);
        int j2 = __float2int_rd(yc2);
        int j3 = __float2int_rd(yc3);

        float2 q0 = p[j0];
        float2 q1 = p[j1];
        float2 q2 = p[j2];
        float2 q3 = p[j3];

        acc0 += fmaf(q0.y, yc0, q0.x);
        acc1 += fmaf(q1.y, yc1, q1.x);
        acc2 += fmaf(q2.y, yc2, q2.x);
        acc3 += fmaf(q3.y, yc3, q3.x);
    }

    const float scale = 0.008726646259971648f;  // pi/360
    float uxx = __fmul_rn(ux, ux);
    float r20 = __fadd_rn(uxx, __fmul_rn(uy0, uy0));
    float r21 = __fadd_rn(uxx, __fmul_rn(uy1, uy1));
    float r22 = __fadd_rn(uxx, __fmul_rn(uy2, uy2));
    float r23 = __fadd_rn(uxx, __fmul_rn(uy3, uy3));

    float* o = out + ((size_t)b * 512 + iy0) * 512 + ix;
    o[0]          = (r20 <= 1.0f) ? acc0 * scale : 0.0f;
    o[8 * 512]    = (r21 <= 1.0f) ? acc1 * scale : 0.0f;
    o[16 * 512]   = (r22 <= 1.0f) ? acc2 * scale : 0.0f;
    o[24 * 512]   = (r23 <= 1.0f) ? acc3 * scale : 0.0f;
}

extern "C" void kernel_launch(void* const* d_in, const int* in_sizes, int n_in,
                              void* d_out, int out_size) {
    const float* x = (const float*)d_in[0];
    float* out = (float*)d_out;

    init_g_kernel<<<2, 512>>>();
    zero_pads_kernel<<<(NROWS * 256 + 255) / 256, 256>>>();
    filt_kernel<<<dim3(DET / 8, BATCH), 192>>>(x);
    bp_kernel<<<dim3(512 / 32, 512 / 32, BATCH), dim3(32, 8)>>>(out);
}

// round 14
// speedup vs baseline: 1.6701x; 1.2661x over previous
#include <cuda_runtime.h>
#include <math.h>

#define BATCH 8
#define DET   512
#define NANG  180
#define PADW  768
#define POFF  128
#define NROWS (BATCH * NANG)

__device__ float g_filt2[1024];
// Lerp lines per padded cell d: (A, B), value(yc) = A + B*yc, yc = yi - 256.
// A = v0 - (d - 384)*B   (384 = POFF + 256)
__device__ float2 g_lines[NROWS * PADW];

__global__ void init_g_kernel() {
    int k = blockIdx.x * blockDim.x + threadIdx.x;
    if (k >= 1024) return;
    int m = k - 512; if (m < 0) m = -m;
    float v = 0.0f;
    if (m == 0) v = 0.5f;
    else if (m & 1) {
        double pm = 3.141592653589793 * (double)m;
        v = (float)(-2.0 / (pm * pm));
    }
    g_filt2[k] = v;
}

// Zero only the pad regions of g_lines: cells [0,128) and [640,768) per row.
__global__ void zero_pads_kernel() {
    int idx = blockIdx.x * blockDim.x + threadIdx.x;
    if (idx >= NROWS * 256) return;
    int row = idx >> 8;
    int c   = idx & 255;
    int d   = (c < 128) ? c : (640 + (c - 128));
    g_lines[row * PADW + d] = make_float2(0.0f, 0.0f);
}

// Ramp filter (symmetric Toeplitz matvec, parity split) fused with line build.
// Computes 9 accumulators (d..d+8) so B = y[d+1]-y[d] is local.
__global__ void __launch_bounds__(192) filt_kernel(const float* __restrict__ x) {
    __shared__ float gs[1024];
    for (int i = threadIdx.x; i < 1024; i += 192) gs[i] = g_filt2[i];
    __syncthreads();

    int b = blockIdx.y;
    int dbase = blockIdx.x * 8;        // always even
    int a = threadIdx.x;
    if (a >= NANG) return;

    const float* xb = x + (size_t)b * DET * NANG + a;
    bool has8 = (dbase < DET - 8);

    float acc0 = 0.5f * xb[(dbase + 0) * NANG];
    float acc1 = 0.5f * xb[(dbase + 1) * NANG];
    float acc2 = 0.5f * xb[(dbase + 2) * NANG];
    float acc3 = 0.5f * xb[(dbase + 3) * NANG];
    float acc4 = 0.5f * xb[(dbase + 4) * NANG];
    float acc5 = 0.5f * xb[(dbase + 5) * NANG];
    float acc6 = 0.5f * xb[(dbase + 6) * NANG];
    float acc7 = 0.5f * xb[(dbase + 7) * NANG];
    float acc8 = has8 ? 0.5f * xb[(dbase + 8) * NANG] : 0.0f;

    const float* gp = gs + 512 + dbase;
    const float* xr = xb;

    #pragma unroll 4
    for (int j = 0; j < DET; j += 2) {
        float xe = xr[0];
        float xo = xr[NANG];
        xr += 2 * NANG;
        const float* g0 = gp - j;
        float gm1 = g0[-1], g1 = g0[1], g3 = g0[3], g5 = g0[5], g7 = g0[7];
        acc1 = fmaf(g1, xe, acc1);
        acc3 = fmaf(g3, xe, acc3);
        acc5 = fmaf(g5, xe, acc5);
        acc7 = fmaf(g7, xe, acc7);
        acc0 = fmaf(gm1, xo, acc0);
        acc2 = fmaf(g1,  xo, acc2);
        acc4 = fmaf(g3,  xo, acc4);
        acc6 = fmaf(g5,  xo, acc6);
        acc8 = fmaf(g7,  xo, acc8);
    }
    if (!has8) acc8 = 0.0f;    // d+8 = 512 is the zero pad

    float2* out = g_lines + ((size_t)b * NANG + a) * PADW + POFF + dbase;
    float fb = (float)(dbase - 256);
    float B0 = acc1 - acc0;  out[0] = make_float2(fmaf(-(fb + 0.f), B0, acc0), B0);
    float B1 = acc2 - acc1;  out[1] = make_float2(fmaf(-(fb + 1.f), B1, acc1), B1);
    float B2 = acc3 - acc2;  out[2] = make_float2(fmaf(-(fb + 2.f), B2, acc2), B2);
    float B3 = acc4 - acc3;  out[3] = make_float2(fmaf(-(fb + 3.f), B3, acc3), B3);
    float B4 = acc5 - acc4;  out[4] = make_float2(fmaf(-(fb + 4.f), B4, acc4), B4);
    float B5 = acc6 - acc5;  out[5] = make_float2(fmaf(-(fb + 5.f), B5, acc5), B5);
    float B6 = acc7 - acc6;  out[6] = make_float2(fmaf(-(fb + 6.f), B6, acc6), B6);
    float B7 = acc8 - acc7;  out[7] = make_float2(fmaf(-(fb + 7.f), B7, acc7), B7);
    if (dbase == 0) {
        // left boundary cell d=127: v0 = 0, v1 = y[0]  ->  B = acc0, A = 257*B
        out[-1] = make_float2(257.0f * acc0, acc0);
    }
}

// Backprojection: 4 pixels/thread, 6-instr taps.
// __launch_bounds__(256, 4): allow ~64 regs so ptxas keeps all unrolled
// gathers in flight (regs=32 at minBlocks-default serialized them).
__global__ void __launch_bounds__(256, 4) bp_kernel(float* __restrict__ out) {
    __shared__ float2 cs[NANG];
    int tid = threadIdx.y * 32 + threadIdx.x;
    if (tid < NANG) {
        float th = (float)tid * 0.017453292519943295f;
        float s, c;
        sincosf(th, &s, &c);
        cs[tid] = make_float2(c * 255.5f, s * 255.5f);
    }
    __syncthreads();

    int b   = blockIdx.z;
    int ix  = blockIdx.x * 32 + threadIdx.x;
    int iy0 = blockIdx.y * 32 + threadIdx.y;   // pixels iy0, +8, +16, +24

    const float step = 2.0f / 511.0f;
    // no-FMA grid coords to track jnp.linspace rounding (mask sensitivity)
    float ux  = __fadd_rn(__fmul_rn((float)ix,        step), -1.0f);
    float uy0 = __fadd_rn(__fmul_rn((float)(iy0),      step), -1.0f);
    float uy1 = __fadd_rn(__fmul_rn((float)(iy0 + 8),  step), -1.0f);
    float uy2 = __fadd_rn(__fmul_rn((float)(iy0 + 16), step), -1.0f);
    float uy3 = __fadd_rn(__fmul_rn((float)(iy0 + 24), step), -1.0f);
    float nuy0 = -uy0, nuy1 = -uy1, nuy2 = -uy2, nuy3 = -uy3;

    // +384 (POFF + 256) folded into the row pointer; j is signed.
    const float2* p = g_lines + (size_t)b * NANG * PADW + 384;

    float acc0 = 0.0f, acc1 = 0.0f, acc2 = 0.0f, acc3 = 0.0f;
    #pragma unroll 4
    for (int a = 0; a < NANG; a++, p += PADW) {
        float2 t = cs[a];
        // yc = ux*t.x - uy*t.y - 0.5   (= yi - 256)
        float xb = fmaf(ux, t.x, -0.5f);

        float yc0 = fmaf(nuy0, t.y, xb);
        float yc1 = fmaf(nuy1, t.y, xb);
        float yc2 = fmaf(nuy2, t.y, xb);
        float yc3 = fmaf(nuy3, t.y, xb);

        int j0 = __float2int_rd(yc0);
        int j1 = __float2int_rd(yc1);
        int j2 = __float2int_rd(yc2);
        int j3 = __float2int_rd(yc3);

        float2 q0 = p[j0];
        float2 q1 = p[j1];
        float2 q2 = p[j2];
        float2 q3 = p[j3];

        acc0 += fmaf(q0.y, yc0, q0.x);
        acc1 += fmaf(q1.y, yc1, q1.x);
        acc2 += fmaf(q2.y, yc2, q2.x);
        acc3 += fmaf(q3.y, yc3, q3.x);
    }

    const float scale = 0.008726646259971648f;  // pi/360
    float uxx = __fmul_rn(ux, ux);
    float r20 = __fadd_rn(uxx, __fmul_rn(uy0, uy0));
    float r21 = __fadd_rn(uxx, __fmul_rn(uy1, uy1));
    float r22 = __fadd_rn(uxx, __fmul_rn(uy2, uy2));
    float r23 = __fadd_rn(uxx, __fmul_rn(uy3, uy3));

    float* o = out + ((size_t)b * 512 + iy0) * 512 + ix;
    o[0]          = (r20 <= 1.0f) ? acc0 * scale : 0.0f;
    o[8 * 512]    = (r21 <= 1.0f) ? acc1 * scale : 0.0f;
    o[16 * 512]   = (r22 <= 1.0f) ? acc2 * scale : 0.0f;
    o[24 * 512]   = (r23 <= 1.0f) ? acc3 * scale : 0.0f;
}

extern "C" void kernel_launch(void* const* d_in, const int* in_sizes, int n_in,
                              void* d_out, int out_size) {
    const float* x = (const float*)d_in[0];
    float* out = (float*)d_out;

    init_g_kernel<<<2, 512>>>();
    zero_pads_kernel<<<(NROWS * 256 + 255) / 256, 256>>>();
    filt_kernel<<<dim3(DET / 8, BATCH), 192>>>(x);
    bp_kernel<<<dim3(512 / 32, 512 / 32, BATCH), dim3(32, 8)>>>(out);
}

// round 15
// speedup vs baseline: 1.7604x; 1.0541x over previous
#include <cuda_runtime.h>
#include <math.h>

#define BATCH 8
#define DET   512
#define NANG  180
#define PADW  768
#define POFF  128
#define NROWS (BATCH * NANG)

__device__ float g_filt2[1024];
// Lerp lines per padded cell d: (A, B), value(yc) = A + B*yc, yc = yi - 256.
// A = v0 - (d - 384)*B   (384 = POFF + 256)
__device__ float2 g_lines[NROWS * PADW];

__global__ void init_g_kernel() {
    int k = blockIdx.x * blockDim.x + threadIdx.x;
    if (k >= 1024) return;
    int m = k - 512; if (m < 0) m = -m;
    float v = 0.0f;
    if (m == 0) v = 0.5f;
    else if (m & 1) {
        double pm = 3.141592653589793 * (double)m;
        v = (float)(-2.0 / (pm * pm));
    }
    g_filt2[k] = v;
}

// Zero only the pad regions of g_lines: cells [0,128) and [640,768) per row.
__global__ void zero_pads_kernel() {
    int idx = blockIdx.x * blockDim.x + threadIdx.x;
    if (idx >= NROWS * 256) return;
    int row = idx >> 8;
    int c   = idx & 255;
    int d   = (c < 128) ? c : (640 + (c - 128));
    g_lines[row * PADW + d] = make_float2(0.0f, 0.0f);
}

// Ramp filter (symmetric Toeplitz matvec, parity split) fused with line build.
// Computes 9 accumulators (d..d+8) so B = y[d+1]-y[d] is local.
__global__ void __launch_bounds__(192) filt_kernel(const float* __restrict__ x) {
    __shared__ float gs[1024];
    for (int i = threadIdx.x; i < 1024; i += 192) gs[i] = g_filt2[i];
    __syncthreads();

    int b = blockIdx.y;
    int dbase = blockIdx.x * 8;        // always even
    int a = threadIdx.x;
    if (a >= NANG) return;

    const float* xb = x + (size_t)b * DET * NANG + a;
    bool has8 = (dbase < DET - 8);

    float acc0 = 0.5f * xb[(dbase + 0) * NANG];
    float acc1 = 0.5f * xb[(dbase + 1) * NANG];
    float acc2 = 0.5f * xb[(dbase + 2) * NANG];
    float acc3 = 0.5f * xb[(dbase + 3) * NANG];
    float acc4 = 0.5f * xb[(dbase + 4) * NANG];
    float acc5 = 0.5f * xb[(dbase + 5) * NANG];
    float acc6 = 0.5f * xb[(dbase + 6) * NANG];
    float acc7 = 0.5f * xb[(dbase + 7) * NANG];
    float acc8 = has8 ? 0.5f * xb[(dbase + 8) * NANG] : 0.0f;

    const float* gp = gs + 512 + dbase;
    const float* xr = xb;

    #pragma unroll 4
    for (int j = 0; j < DET; j += 2) {
        float xe = xr[0];
        float xo = xr[NANG];
        xr += 2 * NANG;
        const float* g0 = gp - j;
        float gm1 = g0[-1], g1 = g0[1], g3 = g0[3], g5 = g0[5], g7 = g0[7];
        acc1 = fmaf(g1, xe, acc1);
        acc3 = fmaf(g3, xe, acc3);
        acc5 = fmaf(g5, xe, acc5);
        acc7 = fmaf(g7, xe, acc7);
        acc0 = fmaf(gm1, xo, acc0);
        acc2 = fmaf(g1,  xo, acc2);
        acc4 = fmaf(g3,  xo, acc4);
        acc6 = fmaf(g5,  xo, acc6);
        acc8 = fmaf(g7,  xo, acc8);
    }
    if (!has8) acc8 = 0.0f;    // d+8 = 512 is the zero pad

    float2* out = g_lines + ((size_t)b * NANG + a) * PADW + POFF + dbase;
    float fb = (float)(dbase - 256);
    float B0 = acc1 - acc0;  out[0] = make_float2(fmaf(-(fb + 0.f), B0, acc0), B0);
    float B1 = acc2 - acc1;  out[1] = make_float2(fmaf(-(fb + 1.f), B1, acc1), B1);
    float B2 = acc3 - acc2;  out[2] = make_float2(fmaf(-(fb + 2.f), B2, acc2), B2);
    float B3 = acc4 - acc3;  out[3] = make_float2(fmaf(-(fb + 3.f), B3, acc3), B3);
    float B4 = acc5 - acc4;  out[4] = make_float2(fmaf(-(fb + 4.f), B4, acc4), B4);
    float B5 = acc6 - acc5;  out[5] = make_float2(fmaf(-(fb + 5.f), B5, acc5), B5);
    float B6 = acc7 - acc6;  out[6] = make_float2(fmaf(-(fb + 6.f), B6, acc6), B6);
    float B7 = acc8 - acc7;  out[7] = make_float2(fmaf(-(fb + 7.f), B7, acc7), B7);
    if (dbase == 0) {
        // left boundary cell d=127: v0 = 0, v1 = y[0]  ->  B = acc0, A = 257*B
        out[-1] = make_float2(257.0f * acc0, acc0);
    }
}

// Backprojection: 4 pixels/thread, 6-instr taps, 64-reg budget (minBlocks=4),
// block-level circle culling for tiles entirely outside the unit circle.
__global__ void __launch_bounds__(256, 4) bp_kernel(float* __restrict__ out) {
    const float step = 2.0f / 511.0f;
    int b   = blockIdx.z;
    int ix  = blockIdx.x * 32 + threadIdx.x;
    int iy0 = blockIdx.y * 32 + threadIdx.y;   // pixels iy0, +8, +16, +24

    // ---- tile cull: min r^2 over the 32x32 tile (u monotone in index) ----
    {
        int x0 = blockIdx.x * 32, y0 = blockIdx.y * 32;
        float ua = __fadd_rn(__fmul_rn((float)x0,        step), -1.0f);
        float ub = __fadd_rn(__fmul_rn((float)(x0 + 31), step), -1.0f);
        float va = __fadd_rn(__fmul_rn((float)y0,        step), -1.0f);
        float vb = __fadd_rn(__fmul_rn((float)(y0 + 31), step), -1.0f);
        float mx = (ua > 0.0f) ? ua : ((ub < 0.0f) ? -ub : 0.0f);
        float my = (va > 0.0f) ? va : ((vb < 0.0f) ? -vb : 0.0f);
        if (mx * mx + my * my > 1.0001f) {
            float* o = out + ((size_t)b * 512 + iy0) * 512 + ix;
            o[0] = 0.0f; o[8 * 512] = 0.0f; o[16 * 512] = 0.0f; o[24 * 512] = 0.0f;
            return;
        }
    }

    __shared__ float2 cs[NANG];
    int tid = threadIdx.y * 32 + threadIdx.x;
    if (tid < NANG) {
        float th = (float)tid * 0.017453292519943295f;
        float s, c;
        sincosf(th, &s, &c);
        cs[tid] = make_float2(c * 255.5f, s * 255.5f);
    }
    __syncthreads();

    // no-FMA grid coords to track jnp.linspace rounding (mask sensitivity)
    float ux  = __fadd_rn(__fmul_rn((float)ix,        step), -1.0f);
    float uy0 = __fadd_rn(__fmul_rn((float)(iy0),      step), -1.0f);
    float uy1 = __fadd_rn(__fmul_rn((float)(iy0 + 8),  step), -1.0f);
    float uy2 = __fadd_rn(__fmul_rn((float)(iy0 + 16), step), -1.0f);
    float uy3 = __fadd_rn(__fmul_rn((float)(iy0 + 24), step), -1.0f);
    float nuy0 = -uy0, nuy1 = -uy1, nuy2 = -uy2, nuy3 = -uy3;

    // +384 (POFF + 256) folded into the row pointer; j is signed.
    const float2* p = g_lines + (size_t)b * NANG * PADW + 384;

    float acc0 = 0.0f, acc1 = 0.0f, acc2 = 0.0f, acc3 = 0.0f;
    #pragma unroll 4
    for (int a = 0; a < NANG; a++, p += PADW) {
        float2 t = cs[a];
        // yc = ux*t.x - uy*t.y - 0.5   (= yi - 256)
        float xb = fmaf(ux, t.x, -0.5f);

        float yc0 = fmaf(nuy0, t.y, xb);
        float yc1 = fmaf(nuy1, t.y, xb);
        float yc2 = fmaf(nuy2, t.y, xb);
        float yc3 = fmaf(nuy3, t.y, xb);

        int j0 = __float2int_rd(yc0);
        int j1 = __float2int_rd(yc1);
        int j2 = __float2int_rd(yc2);
        int j3 = __float2int_rd(yc3);

        float2 q0 = p[j0];
        float2 q1 = p[j1];
        float2 q2 = p[j2];
        float2 q3 = p[j3];

        acc0 += fmaf(q0.y, yc0, q0.x);
        acc1 += fmaf(q1.y, yc1, q1.x);
        acc2 += fmaf(q2.y, yc2, q2.x);
        acc3 += fmaf(q3.y, yc3, q3.x);
    }

    const float scale = 0.008726646259971648f;  // pi/360
    float uxx = __fmul_rn(ux, ux);
    float r20 = __fadd_rn(uxx, __fmul_rn(uy0, uy0));
    float r21 = __fadd_rn(uxx, __fmul_rn(uy1, uy1));
    float r22 = __fadd_rn(uxx, __fmul_rn(uy2, uy2));
    float r23 = __fadd_rn(uxx, __fmul_rn(uy3, uy3));

    float* o = out + ((size_t)b * 512 + iy0) * 512 + ix;
    o[0]          = (r20 <= 1.0f) ? acc0 * scale : 0.0f;
    o[8 * 512]    = (r21 <= 1.0f) ? acc1 * scale : 0.0f;
    o[16 * 512]   = (r22 <= 1.0f) ? acc2 * scale : 0.0f;
    o[24 * 512]   = (r23 <= 1.0f) ? acc3 * scale : 0.0f;
}

extern "C" void kernel_launch(void* const* d_in, const int* in_sizes, int n_in,
                              void* d_out, int out_size) {
    const float* x = (const float*)d_in[0];
    float* out = (float*)d_out;

    init_g_kernel<<<2, 512>>>();
    zero_pads_kernel<<<(NROWS * 256 + 255) / 256, 256>>>();
    filt_kernel<<<dim3(DET / 8, BATCH), 192>>>(x);
    bp_kernel<<<dim3(512 / 32, 512 / 32, BATCH), dim3(32, 8)>>>(out);
}

// round 16
// speedup vs baseline: 1.8917x; 1.0746x over previous
#include <cuda_runtime.h>
#include <math.h>

#define BATCH 8
#define DET   512
#define NANG  180
#define PADW  768
#define POFF  128
#define NROWS (BATCH * NANG)
// byte distance between batch b and b+4 in g_lines
#define BSTRIDE4 ((size_t)4 * NANG * PADW * sizeof(float2))

__device__ float g_filt2[1024];
// Lerp lines per padded cell d: (A, B), value(yc) = A + B*yc, yc = yi - 256.
// A = v0 - (d - 384)*B   (384 = POFF + 256)
__device__ float2 g_lines[NROWS * PADW];

__global__ void init_g_kernel() {
    int k = blockIdx.x * blockDim.x + threadIdx.x;
    if (k >= 1024) return;
    int m = k - 512; if (m < 0) m = -m;
    float v = 0.0f;
    if (m == 0) v = 0.5f;
    else if (m & 1) {
        double pm = 3.141592653589793 * (double)m;
        v = (float)(-2.0 / (pm * pm));
    }
    g_filt2[k] = v;
}

// Zero only the pad regions of g_lines: cells [0,128) and [640,768) per row.
__global__ void zero_pads_kernel() {
    int idx = blockIdx.x * blockDim.x + threadIdx.x;
    if (idx >= NROWS * 256) return;
    int row = idx >> 8;
    int c   = idx & 255;
    int d   = (c < 128) ? c : (640 + (c - 128));
    g_lines[row * PADW + d] = make_float2(0.0f, 0.0f);
}

// Ramp filter (symmetric Toeplitz matvec, parity split) fused with line build.
__global__ void __launch_bounds__(192) filt_kernel(const float* __restrict__ x) {
    __shared__ float gs[1024];
    for (int i = threadIdx.x; i < 1024; i += 192) gs[i] = g_filt2[i];
    __syncthreads();

    int b = blockIdx.y;
    int dbase = blockIdx.x * 8;        // always even
    int a = threadIdx.x;
    if (a >= NANG) return;

    const float* xb = x + (size_t)b * DET * NANG + a;
    bool has8 = (dbase < DET - 8);

    float acc0 = 0.5f * xb[(dbase + 0) * NANG];
    float acc1 = 0.5f * xb[(dbase + 1) * NANG];
    float acc2 = 0.5f * xb[(dbase + 2) * NANG];
    float acc3 = 0.5f * xb[(dbase + 3) * NANG];
    float acc4 = 0.5f * xb[(dbase + 4) * NANG];
    float acc5 = 0.5f * xb[(dbase + 5) * NANG];
    float acc6 = 0.5f * xb[(dbase + 6) * NANG];
    float acc7 = 0.5f * xb[(dbase + 7) * NANG];
    float acc8 = has8 ? 0.5f * xb[(dbase + 8) * NANG] : 0.0f;

    const float* gp = gs + 512 + dbase;
    const float* xr = xb;

    #pragma unroll 4
    for (int j = 0; j < DET; j += 2) {
        float xe = xr[0];
        float xo = xr[NANG];
        xr += 2 * NANG;
        const float* g0 = gp - j;
        float gm1 = g0[-1], g1 = g0[1], g3 = g0[3], g5 = g0[5], g7 = g0[7];
        acc1 = fmaf(g1, xe, acc1);
        acc3 = fmaf(g3, xe, acc3);
        acc5 = fmaf(g5, xe, acc5);
        acc7 = fmaf(g7, xe, acc7);
        acc0 = fmaf(gm1, xo, acc0);
        acc2 = fmaf(g1,  xo, acc2);
        acc4 = fmaf(g3,  xo, acc4);
        acc6 = fmaf(g5,  xo, acc6);
        acc8 = fmaf(g7,  xo, acc8);
    }
    if (!has8) acc8 = 0.0f;    // d+8 = 512 is the zero pad

    float2* out = g_lines + ((size_t)b * NANG + a) * PADW + POFF + dbase;
    float fb = (float)(dbase - 256);
    float B0 = acc1 - acc0;  out[0] = make_float2(fmaf(-(fb + 0.f), B0, acc0), B0);
    float B1 = acc2 - acc1;  out[1] = make_float2(fmaf(-(fb + 1.f), B1, acc1), B1);
    float B2 = acc3 - acc2;  out[2] = make_float2(fmaf(-(fb + 2.f), B2, acc2), B2);
    float B3 = acc4 - acc3;  out[3] = make_float2(fmaf(-(fb + 3.f), B3, acc3), B3);
    float B4 = acc5 - acc4;  out[4] = make_float2(fmaf(-(fb + 4.f), B4, acc4), B4);
    float B5 = acc6 - acc5;  out[5] = make_float2(fmaf(-(fb + 5.f), B5, acc5), B5);
    float B6 = acc7 - acc6;  out[6] = make_float2(fmaf(-(fb + 6.f), B6, acc6), B6);
    float B7 = acc8 - acc7;  out[7] = make_float2(fmaf(-(fb + 7.f), B7, acc7), B7);
    if (dbase == 0) {
        // left boundary cell d=127: v0 = 0, v1 = y[0]  ->  B = acc0, A = 257*B
        out[-1] = make_float2(257.0f * acc0, acc0);
    }
}

// Backprojection: 4 pixels/thread x 2 batches/block (b, b+4).
// Index chain (FFMA/F2I/IMAD) computed once, feeds both batches' loads via a
// constant byte offset folded into the LDG immediate.
__global__ void __launch_bounds__(256, 4) bp_kernel(float* __restrict__ out) {
    const float step = 2.0f / 511.0f;
    int b   = blockIdx.z;              // batches b and b+4
    int ix  = blockIdx.x * 32 + threadIdx.x;
    int iy0 = blockIdx.y * 32 + threadIdx.y;   // pixels iy0, +8, +16, +24

    // ---- tile cull: min r^2 over the 32x32 tile (u monotone in index) ----
    {
        int x0 = blockIdx.x * 32, y0 = blockIdx.y * 32;
        float ua = __fadd_rn(__fmul_rn((float)x0,        step), -1.0f);
        float ub = __fadd_rn(__fmul_rn((float)(x0 + 31), step), -1.0f);
        float va = __fadd_rn(__fmul_rn((float)y0,        step), -1.0f);
        float vb = __fadd_rn(__fmul_rn((float)(y0 + 31), step), -1.0f);
        float mx = (ua > 0.0f) ? ua : ((ub < 0.0f) ? -ub : 0.0f);
        float my = (va > 0.0f) ? va : ((vb < 0.0f) ? -vb : 0.0f);
        if (mx * mx + my * my > 1.0001f) {
            float* o0 = out + ((size_t)b * 512 + iy0) * 512 + ix;
            float* o1 = o0 + (size_t)4 * 512 * 512;
            #pragma unroll
            for (int k = 0; k < 4; k++) { o0[k * 8 * 512] = 0.0f; o1[k * 8 * 512] = 0.0f; }
            return;
        }
    }

    __shared__ float2 cs[NANG];
    int tid = threadIdx.y * 32 + threadIdx.x;
    if (tid < NANG) {
        float th = (float)tid * 0.017453292519943295f;
        float s, c;
        sincosf(th, &s, &c);
        cs[tid] = make_float2(c * 255.5f, s * 255.5f);
    }
    __syncthreads();

    // no-FMA grid coords to track jnp.linspace rounding (mask sensitivity)
    float ux  = __fadd_rn(__fmul_rn((float)ix,        step), -1.0f);
    float uy0 = __fadd_rn(__fmul_rn((float)(iy0),      step), -1.0f);
    float uy1 = __fadd_rn(__fmul_rn((float)(iy0 + 8),  step), -1.0f);
    float uy2 = __fadd_rn(__fmul_rn((float)(iy0 + 16), step), -1.0f);
    float uy3 = __fadd_rn(__fmul_rn((float)(iy0 + 24), step), -1.0f);
    float nuy0 = -uy0, nuy1 = -uy1, nuy2 = -uy2, nuy3 = -uy3;

    // +384 (POFF + 256) folded into the row pointer; j is signed.
    const float2* p = g_lines + (size_t)b * NANG * PADW + 384;

    float acc00 = 0.0f, acc01 = 0.0f, acc02 = 0.0f, acc03 = 0.0f;
    float acc10 = 0.0f, acc11 = 0.0f, acc12 = 0.0f, acc13 = 0.0f;
    #pragma unroll 2
    for (int a = 0; a < NANG; a++, p += PADW) {
        float2 t = cs[a];
        // yc = ux*t.x - uy*t.y - 0.5   (= yi - 256)
        float xb = fmaf(ux, t.x, -0.5f);

        float yc0 = fmaf(nuy0, t.y, xb);
        float yc1 = fmaf(nuy1, t.y, xb);
        float yc2 = fmaf(nuy2, t.y, xb);
        float yc3 = fmaf(nuy3, t.y, xb);

        int j0 = __float2int_rd(yc0);
        int j1 = __float2int_rd(yc1);
        int j2 = __float2int_rd(yc2);
        int j3 = __float2int_rd(yc3);

        const char* a0 = (const char*)(p + j0);
        const char* a1 = (const char*)(p + j1);
        const char* a2 = (const char*)(p + j2);
        const char* a3 = (const char*)(p + j3);

        float2 q00 = *(const float2*)(a0);
        float2 q01 = *(const float2*)(a1);
        float2 q02 = *(const float2*)(a2);
        float2 q03 = *(const float2*)(a3);
        float2 q10 = *(const float2*)(a0 + BSTRIDE4);
        float2 q11 = *(const float2*)(a1 + BSTRIDE4);
        float2 q12 = *(const float2*)(a2 + BSTRIDE4);
        float2 q13 = *(const float2*)(a3 + BSTRIDE4);

        acc00 += fmaf(q00.y, yc0, q00.x);
        acc01 += fmaf(q01.y, yc1, q01.x);
        acc02 += fmaf(q02.y, yc2, q02.x);
        acc03 += fmaf(q03.y, yc3, q03.x);
        acc10 += fmaf(q10.y, yc0, q10.x);
        acc11 += fmaf(q11.y, yc1, q11.x);
        acc12 += fmaf(q12.y, yc2, q12.x);
        acc13 += fmaf(q13.y, yc3, q13.x);
    }

    const float scale = 0.008726646259971648f;  // pi/360
    float uxx = __fmul_rn(ux, ux);
    float r20 = __fadd_rn(uxx, __fmul_rn(uy0, uy0));
    float r21 = __fadd_rn(uxx, __fmul_rn(uy1, uy1));
    float r22 = __fadd_rn(uxx, __fmul_rn(uy2, uy2));
    float r23 = __fadd_rn(uxx, __fmul_rn(uy3, uy3));

    float* o0 = out + ((size_t)b * 512 + iy0) * 512 + ix;
    float* o1 = o0 + (size_t)4 * 512 * 512;
    o0[0]        = (r20 <= 1.0f) ? acc00 * scale : 0.0f;
    o0[8 * 512]  = (r21 <= 1.0f) ? acc01 * scale : 0.0f;
    o0[16 * 512] = (r22 <= 1.0f) ? acc02 * scale : 0.0f;
    o0[24 * 512] = (r23 <= 1.0f) ? acc03 * scale : 0.0f;
    o1[0]        = (r20 <= 1.0f) ? acc10 * scale : 0.0f;
    o1[8 * 512]  = (r21 <= 1.0f) ? acc11 * scale : 0.0f;
    o1[16 * 512] = (r22 <= 1.0f) ? acc12 * scale : 0.0f;
    o1[24 * 512] = (r23 <= 1.0f) ? acc13 * scale : 0.0f;
}

extern "C" void kernel_launch(void* const* d_in, const int* in_sizes, int n_in,
                              void* d_out, int out_size) {
    const float* x = (const float*)d_in[0];
    float* out = (float*)d_out;

    init_g_kernel<<<2, 512>>>();
    zero_pads_kernel<<<(NROWS * 256 + 255) / 256, 256>>>();
    filt_kernel<<<dim3(DET / 8, BATCH), 192>>>(x);
    bp_kernel<<<dim3(512 / 32, 512 / 32, BATCH / 2), dim3(32, 8)>>>(out);
}